// round 12
// baseline (speedup 1.0000x reference)
#include <cuda_runtime.h>
#include <cuda_fp16.h>
#include <cstdint>

#define B_   64
#define N_   128
#define F_   128
#define R_   64
#define H_   256
#define L_   3
#define ROWS (B_*N_)

// half images: row strides 136 halves (K=128), 72 halves (K=64)
#define XSB 17408   // prep-side 64-row x image (== two 32-row tiles, contiguous)
#define CFB 17408
#define DSB 9216
#define DFB 9216
#define FCB 18432
// dtnn per-CTA tile sizes (32 rows)
#define XTB 8704
#define DTB 4608

__device__ uint4 g_cf[12 * CFB / 16];
__device__ uint4 g_df[12 * DFB / 16];
__device__ uint4 g_fc[12 * FCB / 16];
__device__ uint4 g_xs[128 * XSB / 16];
__device__ uint4 g_ds[128 * DSB / 16];
__device__ float g_v[F_];

__device__ __forceinline__ float tanh_fast(float x) {
    float r; asm("tanh.approx.f32 %0, %1;" : "=f"(r) : "f"(x)); return r;
}
__device__ __forceinline__ uint32_t f2h2(float lo, float hi) {
    __half2 h = __floats2half2_rn(lo, hi);
    return *(uint32_t*)&h;
}
__device__ __forceinline__ void mma16(float* d, uint32_t a0, uint32_t a1, uint32_t a2, uint32_t a3,
                                      uint32_t b0, uint32_t b1) {
    asm volatile(
        "mma.sync.aligned.m16n8k16.row.col.f32.f16.f16.f32 "
        "{%0,%1,%2,%3},{%4,%5,%6,%7},{%8,%9},{%0,%1,%2,%3};"
        : "+f"(d[0]), "+f"(d[1]), "+f"(d[2]), "+f"(d[3])
        : "r"(a0), "r"(a1), "r"(a2), "r"(a3), "r"(b0), "r"(b1));
}
#define LDSM4(r0,r1,r2,r3,addr) \
    asm volatile("ldmatrix.sync.aligned.m8n8.x4.shared.b16 {%0,%1,%2,%3}, [%4];" \
        : "=r"(r0), "=r"(r1), "=r"(r2), "=r"(r3) : "r"(addr))
__device__ __forceinline__ void cpa16(uint32_t dst, const uint4* src) {
    asm volatile("cp.async.ca.shared.global [%0], [%1], 16;" :: "r"(dst), "l"(src));
}
#define CP_COMMIT() asm volatile("cp.async.commit_group;" ::: "memory")
template<int N>
__device__ __forceinline__ void cp_wait() {
    asm volatile("cp.async.wait_group %0;" :: "n"(N) : "memory");
}
template<int NC>
__device__ __forceinline__ void copy_img(uint32_t dst, const uint4* __restrict__ src, int tid) {
    #pragma unroll
    for (int i = tid; i < NC; i += 256) cpa16(dst + i * 16, src + i);
}
__device__ __forceinline__ uint32_t smem_u32(const void* p) {
    uint32_t a;
    asm("{ .reg .u64 t; cvta.to.shared.u64 t, %1; cvt.u32.u64 %0, t; }" : "=r"(a) : "l"(p));
    return a;
}
__device__ __forceinline__ void pack8(char* dst, const float* __restrict__ src) {
    float4 a = *(const float4*)src;
    float4 b = *(const float4*)(src + 4);
    uint4 o;
    o.x = f2h2(a.x, a.y); o.y = f2h2(a.z, a.w);
    o.z = f2h2(b.x, b.y); o.w = f2h2(b.z, b.w);
    *(uint4*)dst = o;
}

// ---------------- Kernel A: prep (141 blocks) + streaming reduce (8192 blocks) ----------------
__global__ void prep_reduce_kernel(const float* __restrict__ dist, const float* __restrict__ x,
                                   const float* __restrict__ Wcf_w, const float* __restrict__ Wdf_w,
                                   const float* __restrict__ Wfc_w,
                                   const float* __restrict__ fc0_w, const float* __restrict__ fc0_b,
                                   const float* __restrict__ out_w, const float* __restrict__ out_b,
                                   float* __restrict__ out) {
    int bid = blockIdx.x, tid = threadIdx.x;
    if (bid >= 141) {                      // ---- reduce one row (32KB) ----
        int row = bid - 141;
        const float4* p = (const float4*)(dist + (size_t)row * (N_ * R_));
        float4 acc = make_float4(0.f, 0.f, 0.f, 0.f);
        #pragma unroll
        for (int t = 0; t < 8; t++) {
            float4 v = __ldcs(&p[tid + t * 256]);
            acc.x += v.x; acc.y += v.y; acc.z += v.z; acc.w += v.w;
        }
        __shared__ float4 s[256];
        s[tid] = acc;
        __syncthreads();
        if (tid < 16) {
            float4 a = s[tid];
            #pragma unroll
            for (int m = 1; m < 16; m++) {
                float4 b = s[tid + 16 * m];
                a.x += b.x; a.y += b.y; a.z += b.z; a.w += b.w;
            }
            char* dp = (char*)g_ds + (row >> 6) * DSB + (row & 63) * 144 + tid * 8;
            uint2 o; o.x = f2h2(a.x, a.y); o.y = f2h2(a.z, a.w);
            *(uint2*)dp = o;
        }
    } else if (bid < 128) {                // ---- x tile image ----
        char* dst = (char*)g_xs + (size_t)bid * XSB;
        const float* src = x + (size_t)bid * 64 * 128;
        #pragma unroll
        for (int i = 0; i < 4; i++) {
            int oct = tid + i * 256;
            int row = oct >> 4, ko = oct & 15;
            pack8(dst + row * 272 + ko * 16, src + row * 128 + ko * 8);
        }
    } else if (bid < 140) {                // ---- weight chunk images ----
        int wi = bid - 128, l = wi >> 2, c = wi & 3;
        char* dcf = (char*)g_cf + (size_t)wi * CFB;
        const float* scf = Wcf_w + (size_t)l * 32768 + c * 8192;
        #pragma unroll
        for (int i = 0; i < 4; i++) {
            int oct = tid + i * 256;
            int row = oct >> 4, ko = oct & 15;
            pack8(dcf + row * 272 + ko * 16, scf + row * 128 + ko * 8);
        }
        char* ddf = (char*)g_df + (size_t)wi * DFB;
        const float* sdf = Wdf_w + (size_t)l * 16384 + c * 4096;
        #pragma unroll
        for (int i = 0; i < 2; i++) {
            int oct = tid + i * 256;
            int row = oct >> 3, ko = oct & 7;
            pack8(ddf + row * 144 + ko * 16, sdf + row * 64 + ko * 8);
        }
        char* dfc = (char*)g_fc + (size_t)wi * FCB;
        const float* sfc = Wfc_w + (size_t)l * 32768 + c * 64;
        #pragma unroll
        for (int i = 0; i < 4; i++) {
            int oct = tid + i * 256;
            int row = oct >> 3, ko = oct & 7;
            pack8(dfc + row * 144 + ko * 16, sfc + row * 256 + ko * 8);
        }
    } else {                               // ---- fold head + init out ----
        if (tid < 128) {
            float a = 0.f;
            #pragma unroll 8
            for (int c = 0; c < 256; c++) a += out_w[c] * fc0_w[c * F_ + tid];
            g_v[tid] = a;
        }
        __shared__ float cs;
        if (tid == 0) {
            float s = out_b[0];
            for (int c = 0; c < 256; c++) s += out_w[c] * fc0_b[c];
            cs = s;
        }
        __syncthreads();
        if (tid < B_) out[tid] = cs;
    }
}

// ---------------- Kernel B: fp16 mma, 256 CTAs x 32 rows, 2 CTAs/SM ----------------
enum {
    OXS  = 0,              // Xs [32][136h]
    ODS  = OXS + XTB,      // 8704
    OPB  = ODS + DTB,      // 13312  Pb [32][72h]
    OCF0 = OPB + DTB,      // 17920
    OCF1 = OCF0 + CFB,     // 35328
    ODF0 = OCF1 + CFB,     // 52736
    ODF1 = ODF0 + DFB,     // 61952
    OFC  = ODF1 + DFB,     // 71168
    OBC  = OFC + FCB,      // 89600
    OBD  = OBC + 1024,
    OVV  = OBD + 1024,
    ORD  = OVV + 512,
    SMEMB = ORD + 1024     // 93184 B -> 2 CTAs/SM
};

__global__ __launch_bounds__(256, 2)
void dtnn_mma_kernel(const float* __restrict__ Wcf_b, const float* __restrict__ Wdf_b,
                     float* __restrict__ out) {
    extern __shared__ char smc[];
    float* bc = (float*)(smc + OBC);
    float* bd = (float*)(smc + OBD);
    float* vv = (float*)(smc + OVV);
    float* rd = (float*)(smc + ORD);
    __half2* Ph = (__half2*)(smc + OPB);
    __half2* Xh = (__half2*)(smc + OXS);
    uint32_t sb = smem_u32(smc);

    int tid = threadIdx.x, lane = tid & 31, w = tid >> 5;
    int g = lane >> 2, t = lane & 3;
    int wm = w & 1, wn = w >> 1;          // 2 (M=2x16 rows) x 4 (N)
    int bid = blockIdx.x;

    int lrow = (lane & 7) + ((lane >> 3) & 1) * 8;
    int lchk = ((lane >> 4) & 1) * 16;
    uint32_t aX0 = sb + OXS + (wm * 16 + lrow) * 272 + lchk;
    uint32_t aD0 = sb + ODS + (wm * 16 + lrow) * 144 + lchk;
    uint32_t aP0 = sb + OPB + (wm * 16 + lrow) * 144 + lchk;
    uint32_t bF0 = sb + OFC + (wn * 32 + lrow) * 144 + lchk;
    uint32_t bF1 = bF0 + 16 * 144;

    copy_img<XTB/16>(sb + OXS, g_xs + bid * (XTB/16), tid);
    copy_img<DTB/16>(sb + ODS, g_ds + bid * (DTB/16), tid);
    copy_img<CFB/16>(sb + OCF0, g_cf, tid);
    copy_img<DFB/16>(sb + ODF0, g_df, tid);
    CP_COMMIT();
    bc[tid] = Wcf_b[tid];
    bd[tid] = 128.f * Wdf_b[tid];
    if (tid < 128) vv[tid] = g_v[tid];
    cp_wait<0>();
    __syncthreads();

    float hacc[4][4] = {};
    float pool = 0.f;

    for (int i = 0; i < 12; i++) {
        int l = i >> 2, c = i & 3, buf = i & 1;

        // commit order: [CFDF(i+1)] then [FC(i)]
        if (i < 11) {
            copy_img<CFB/16>(sb + (buf ? OCF0 : OCF1), g_cf + (i + 1) * (CFB/16), tid);
            copy_img<DFB/16>(sb + (buf ? ODF0 : ODF1), g_df + (i + 1) * (DFB/16), tid);
            CP_COMMIT();
        }
        copy_img<FCB/16>(sb + OFC, g_fc + i * (FCB/16), tid);
        CP_COMMIT();
        // guarantee CFDF(i) complete for everyone
        if (i < 11) cp_wait<2>(); else cp_wait<1>();
        __syncthreads();

        uint32_t bCF = sb + (buf ? OCF1 : OCF0) + (wn * 16 + lrow) * 272 + lchk;
        uint32_t bDF = sb + (buf ? ODF1 : ODF0) + (wn * 16 + lrow) * 144 + lchk;

        float cf[2][4] = {}, df[2][4] = {};
        #pragma unroll
        for (int ks = 0; ks < 8; ks++) {       // cf: Xs[32x128] @ CF^T
            uint32_t a0, a1, a2, a3, b0, b1, b2, b3;
            LDSM4(a0, a1, a2, a3, aX0 + ks * 32);
            LDSM4(b0, b1, b2, b3, bCF + ks * 32);
            mma16(cf[0], a0, a1, a2, a3, b0, b2);
            mma16(cf[1], a0, a1, a2, a3, b1, b3);
        }
        #pragma unroll
        for (int ks = 0; ks < 4; ks++) {       // df: Ds[32x64] @ DF^T
            uint32_t a0, a1, a2, a3, b0, b1, b2, b3;
            LDSM4(a0, a1, a2, a3, aD0 + ks * 32);
            LDSM4(b0, b1, b2, b3, bDF + ks * 32);
            mma16(df[0], a0, a1, a2, a3, b0, b2);
            mma16(df[1], a0, a1, a2, a3, b1, b3);
        }
        // P = (cf+bc)*(df+128*bd) -> Pb (fp16)
        int hc = c * 64;
        #pragma unroll
        for (int nt = 0; nt < 2; nt++) {
            int col = wn * 16 + nt * 8 + 2 * t;
            int row = wm * 16 + g;
            float b0c = bc[hc + col], b1c = bc[hc + col + 1];
            float b0d = bd[hc + col], b1d = bd[hc + col + 1];
            float* f4 = cf[nt];
            float* d4 = df[nt];
            Ph[(row * 72 + col) >> 1] =
                __floats2half2_rn((f4[0] + b0c) * (d4[0] + b0d), (f4[1] + b1c) * (d4[1] + b1d));
            Ph[((row + 8) * 72 + col) >> 1] =
                __floats2half2_rn((f4[2] + b0c) * (d4[2] + b0d), (f4[3] + b1c) * (d4[3] + b1d));
        }

        if (i < 11) cp_wait<1>(); else cp_wait<0>();   // FC(i) complete
        __syncthreads();                                // Pb + FCb visible

        #pragma unroll
        for (int ks = 0; ks < 4; ks++) {       // fc: Pb[32x64] @ FC^T (accumulate)
            uint32_t p0, p1, p2, p3, b0, b1, b2, b3, c0, c1, c2, c3;
            LDSM4(p0, p1, p2, p3, aP0 + ks * 32);
            LDSM4(b0, b1, b2, b3, bF0 + ks * 32);
            LDSM4(c0, c1, c2, c3, bF1 + ks * 32);
            mma16(hacc[0], p0, p1, p2, p3, b0, b2);
            mma16(hacc[1], p0, p1, p2, p3, b1, b3);
            mma16(hacc[2], p0, p1, p2, p3, c0, c2);
            mma16(hacc[3], p0, p1, p2, p3, c1, c3);
        }

        if (c == 3) {
            if (l < 2) {
                #pragma unroll
                for (int nt = 0; nt < 4; nt++) {
                    int col = wn * 32 + nt * 8 + 2 * t;
                    int row = wm * 16 + g;
                    float* h4 = hacc[nt];
                    Xh[(row * 136 + col) >> 1] =
                        __floats2half2_rn(h4[0] + tanh_fast(h4[0]), h4[1] + tanh_fast(h4[1]));
                    Xh[((row + 8) * 136 + col) >> 1] =
                        __floats2half2_rn(h4[2] + tanh_fast(h4[2]), h4[3] + tanh_fast(h4[3]));
                }
                bc[tid] = Wcf_b[(l + 1) * H_ + tid];
                bd[tid] = 128.f * Wdf_b[(l + 1) * H_ + tid];
                #pragma unroll
                for (int nt = 0; nt < 4; nt++)
                #pragma unroll
                for (int e = 0; e < 4; e++) hacc[nt][e] = 0.f;
            } else {
                #pragma unroll
                for (int nt = 0; nt < 4; nt++) {
                    int col = wn * 32 + nt * 8 + 2 * t;
                    float* h4 = hacc[nt];
                    pool += (h4[0] + tanh_fast(h4[0])) * vv[col];
                    pool += (h4[1] + tanh_fast(h4[1])) * vv[col + 1];
                    pool += (h4[2] + tanh_fast(h4[2])) * vv[col];
                    pool += (h4[3] + tanh_fast(h4[3])) * vv[col + 1];
                }
                rd[tid] = pool;
                __syncthreads();
                for (int s = 128; s > 0; s >>= 1) {
                    if (tid < s) rd[tid] += rd[tid + s];
                    __syncthreads();
                }
                if (tid == 0) atomicAdd(out + (bid >> 2), rd[0]);
            }
        }
        if (i < 11) { __syncthreads(); }   // protect buffers reused next iter
    }
}

// ---------------- launch ----------------
extern "C" void kernel_launch(void* const* d_in, const int* in_sizes, int n_in,
                              void* d_out, int out_size) {
    const float* x     = (const float*)d_in[0];
    const float* dist  = (const float*)d_in[1];
    const float* Wcf_w = (const float*)d_in[2];
    const float* Wcf_b = (const float*)d_in[3];
    const float* Wdf_w = (const float*)d_in[4];
    const float* Wdf_b = (const float*)d_in[5];
    const float* Wfc_w = (const float*)d_in[6];
    const float* fc0_w = (const float*)d_in[7];
    const float* fc0_b = (const float*)d_in[8];
    const float* out_w = (const float*)d_in[9];
    const float* out_b = (const float*)d_in[10];
    float* out = (float*)d_out;

    cudaFuncSetAttribute(dtnn_mma_kernel,
                         cudaFuncAttributeMaxDynamicSharedMemorySize, SMEMB);

    prep_reduce_kernel<<<141 + ROWS, 256>>>(dist, x, Wcf_w, Wdf_w, Wfc_w,
                                            fc0_w, fc0_b, out_w, out_b, out);
    dtnn_mma_kernel<<<256, 256, SMEMB>>>(Wcf_b, Wdf_b, out);
}

// round 13
// speedup vs baseline: 1.0286x; 1.0286x over previous
#include <cuda_runtime.h>
#include <cuda_fp16.h>
#include <cstdint>

#define B_   64
#define N_   128
#define F_   128
#define R_   64
#define H_   256
#define L_   3
#define ROWS (B_*N_)

// half images: row strides 136 halves (K=128), 72 halves (K=64)
#define XSB 17408   // 64*136*2
#define CFB 17408
#define DSB 9216    // 64*72*2
#define DFB 9216
#define FCB 18432   // 128*72*2

__device__ uint4 g_cf[12 * CFB / 16];
__device__ uint4 g_df[12 * DFB / 16];
__device__ uint4 g_fc[12 * FCB / 16];
__device__ uint4 g_xs[128 * XSB / 16];
__device__ uint4 g_ds[128 * DSB / 16];
__device__ float g_v[F_];

__device__ __forceinline__ float tanh_fast(float x) {
    float r; asm("tanh.approx.f32 %0, %1;" : "=f"(r) : "f"(x)); return r;
}
__device__ __forceinline__ uint32_t f2h2(float lo, float hi) {
    __half2 h = __floats2half2_rn(lo, hi);
    return *(uint32_t*)&h;
}
__device__ __forceinline__ void mma16(float* d, uint32_t a0, uint32_t a1, uint32_t a2, uint32_t a3,
                                      uint32_t b0, uint32_t b1) {
    asm volatile(
        "mma.sync.aligned.m16n8k16.row.col.f32.f16.f16.f32 "
        "{%0,%1,%2,%3},{%4,%5,%6,%7},{%8,%9},{%0,%1,%2,%3};"
        : "+f"(d[0]), "+f"(d[1]), "+f"(d[2]), "+f"(d[3])
        : "r"(a0), "r"(a1), "r"(a2), "r"(a3), "r"(b0), "r"(b1));
}
#define LDSM4(r0,r1,r2,r3,addr) \
    asm volatile("ldmatrix.sync.aligned.m8n8.x4.shared.b16 {%0,%1,%2,%3}, [%4];" \
        : "=r"(r0), "=r"(r1), "=r"(r2), "=r"(r3) : "r"(addr))
__device__ __forceinline__ void cpa16(uint32_t dst, const uint4* src) {
    asm volatile("cp.async.ca.shared.global [%0], [%1], 16;" :: "r"(dst), "l"(src));
}
#define CP_COMMIT() asm volatile("cp.async.commit_group;" ::: "memory")
template<int N>
__device__ __forceinline__ void cp_wait() {
    asm volatile("cp.async.wait_group %0;" :: "n"(N) : "memory");
}
template<int NC, int NT>
__device__ __forceinline__ void copy_img(uint32_t dst, const uint4* __restrict__ src, int tid) {
    #pragma unroll
    for (int i = tid; i < NC; i += NT) cpa16(dst + i * 16, src + i);
}
__device__ __forceinline__ uint32_t smem_u32(const void* p) {
    uint32_t a;
    asm("{ .reg .u64 t; cvta.to.shared.u64 t, %1; cvt.u32.u64 %0, t; }" : "=r"(a) : "l"(p));
    return a;
}
__device__ __forceinline__ void pack8(char* dst, const float* __restrict__ src) {
    float4 a = *(const float4*)src;
    float4 b = *(const float4*)(src + 4);
    uint4 o;
    o.x = f2h2(a.x, a.y); o.y = f2h2(a.z, a.w);
    o.z = f2h2(b.x, b.y); o.w = f2h2(b.z, b.w);
    *(uint4*)dst = o;
}

// ---------------- Kernel A: prep (141 blocks) + streaming reduce (8192 blocks) ----------------
__global__ void prep_reduce_kernel(const float* __restrict__ dist, const float* __restrict__ x,
                                   const float* __restrict__ Wcf_w, const float* __restrict__ Wdf_w,
                                   const float* __restrict__ Wfc_w,
                                   const float* __restrict__ fc0_w, const float* __restrict__ fc0_b,
                                   const float* __restrict__ out_w, const float* __restrict__ out_b,
                                   float* __restrict__ out) {
    int bid = blockIdx.x, tid = threadIdx.x;
    if (bid >= 141) {                      // ---- reduce one row (32KB) ----
        int row = bid - 141;
        const float4* p = (const float4*)(dist + (size_t)row * (N_ * R_));
        float4 acc = make_float4(0.f, 0.f, 0.f, 0.f);
        #pragma unroll
        for (int t = 0; t < 8; t++) {
            float4 v = __ldcs(&p[tid + t * 256]);
            acc.x += v.x; acc.y += v.y; acc.z += v.z; acc.w += v.w;
        }
        __shared__ float4 s[256];
        s[tid] = acc;
        __syncthreads();
        if (tid < 16) {
            float4 a = s[tid];
            #pragma unroll
            for (int m = 1; m < 16; m++) {
                float4 b = s[tid + 16 * m];
                a.x += b.x; a.y += b.y; a.z += b.z; a.w += b.w;
            }
            char* dp = (char*)g_ds + (row >> 6) * DSB + (row & 63) * 144 + tid * 8;
            uint2 o; o.x = f2h2(a.x, a.y); o.y = f2h2(a.z, a.w);
            *(uint2*)dp = o;
        }
    } else if (bid < 128) {                // ---- x tile image ----
        char* dst = (char*)g_xs + (size_t)bid * XSB;
        const float* src = x + (size_t)bid * 64 * 128;
        #pragma unroll
        for (int i = 0; i < 4; i++) {
            int oct = tid + i * 256;
            int row = oct >> 4, ko = oct & 15;
            pack8(dst + row * 272 + ko * 16, src + row * 128 + ko * 8);
        }
    } else if (bid < 140) {                // ---- weight chunk images ----
        int wi = bid - 128, l = wi >> 2, c = wi & 3;
        char* dcf = (char*)g_cf + (size_t)wi * CFB;
        const float* scf = Wcf_w + (size_t)l * 32768 + c * 8192;
        #pragma unroll
        for (int i = 0; i < 4; i++) {
            int oct = tid + i * 256;
            int row = oct >> 4, ko = oct & 15;
            pack8(dcf + row * 272 + ko * 16, scf + row * 128 + ko * 8);
        }
        char* ddf = (char*)g_df + (size_t)wi * DFB;
        const float* sdf = Wdf_w + (size_t)l * 16384 + c * 4096;
        #pragma unroll
        for (int i = 0; i < 2; i++) {
            int oct = tid + i * 256;
            int row = oct >> 3, ko = oct & 7;
            pack8(ddf + row * 144 + ko * 16, sdf + row * 64 + ko * 8);
        }
        char* dfc = (char*)g_fc + (size_t)wi * FCB;
        const float* sfc = Wfc_w + (size_t)l * 32768 + c * 64;
        #pragma unroll
        for (int i = 0; i < 4; i++) {
            int oct = tid + i * 256;
            int row = oct >> 3, ko = oct & 7;
            pack8(dfc + row * 144 + ko * 16, sfc + row * 256 + ko * 8);
        }
    } else {                               // ---- fold head + init out ----
        if (tid < 128) {
            float a = 0.f;
            #pragma unroll 8
            for (int c = 0; c < 256; c++) a += out_w[c] * fc0_w[c * F_ + tid];
            g_v[tid] = a;
        }
        __shared__ float cs;
        if (tid == 0) {
            float s = out_b[0];
            for (int c = 0; c < 256; c++) s += out_w[c] * fc0_b[c];
            cs = s;
        }
        __syncthreads();
        if (tid < B_) out[tid] = cs;
    }
}

// ---------------- Kernel B: fp16 mma, 128 CTAs x 64 rows, 512 threads ----------------
enum {
    OXS  = 0,
    ODS  = OXS + XSB,     // 17408
    OPB  = ODS + DSB,     // 26624
    OCF0 = OPB + DSB,     // 35840
    OCF1 = OCF0 + CFB,    // 53248
    ODF0 = OCF1 + CFB,    // 70656
    ODF1 = ODF0 + DFB,    // 79872
    OFC  = ODF1 + DFB,    // 89088
    OBC  = OFC + FCB,     // 107520
    OBD  = OBC + 1024,
    OVV  = OBD + 1024,
    ORD  = OVV + 512,
    SMEMB = ORD + 2048    // 112640 B
};

__global__ __launch_bounds__(512, 1)
void dtnn_mma_kernel(const float* __restrict__ Wcf_b, const float* __restrict__ Wdf_b,
                     float* __restrict__ out) {
    extern __shared__ char smc[];
    float* bc = (float*)(smc + OBC);
    float* bd = (float*)(smc + OBD);
    float* vv = (float*)(smc + OVV);
    float* rd = (float*)(smc + ORD);
    __half2* Ph = (__half2*)(smc + OPB);
    __half2* Xh = (__half2*)(smc + OXS);
    uint32_t sb = smem_u32(smc);

    int tid = threadIdx.x, lane = tid & 31, w = tid >> 5;
    int g = lane >> 2, t = lane & 3;
    int wm = w & 3, wn = w >> 2;          // warp grid: 4 (M=16 rows) x 4 (N)
    int bid = blockIdx.x;

    int lrow = (lane & 7) + ((lane >> 3) & 1) * 8;
    int lchk = ((lane >> 4) & 1) * 16;
    uint32_t aX0 = sb + OXS + (wm * 16 + lrow) * 272 + lchk;
    uint32_t aD0 = sb + ODS + (wm * 16 + lrow) * 144 + lchk;
    uint32_t aP0 = sb + OPB + (wm * 16 + lrow) * 144 + lchk;
    uint32_t bF0 = sb + OFC + (wn * 32 + lrow) * 144 + lchk;
    uint32_t bF1 = bF0 + 16 * 144;

    copy_img<XSB/16, 512>(sb + OXS, g_xs + bid * (XSB/16), tid);
    copy_img<DSB/16, 512>(sb + ODS, g_ds + bid * (DSB/16), tid);
    copy_img<CFB/16, 512>(sb + OCF0, g_cf, tid);
    copy_img<DFB/16, 512>(sb + ODF0, g_df, tid);
    CP_COMMIT();
    if (tid < 256) {
        bc[tid] = Wcf_b[tid];
        bd[tid] = 128.f * Wdf_b[tid];
    }
    if (tid < 128) vv[tid] = g_v[tid];
    cp_wait<0>();
    __syncthreads();

    float hacc[4][4] = {};
    float pool = 0.f;

    for (int i = 0; i < 12; i++) {
        int l = i >> 2, c = i & 3, buf = i & 1;

        // commit order: [CFDF(i+1)] then [FC(i)]
        if (i < 11) {
            copy_img<CFB/16, 512>(sb + (buf ? OCF0 : OCF1), g_cf + (i + 1) * (CFB/16), tid);
            copy_img<DFB/16, 512>(sb + (buf ? ODF0 : ODF1), g_df + (i + 1) * (DFB/16), tid);
            CP_COMMIT();
        }
        copy_img<FCB/16, 512>(sb + OFC, g_fc + i * (FCB/16), tid);
        CP_COMMIT();
        if (i < 11) cp_wait<2>(); else cp_wait<1>();   // CFDF(i) complete
        __syncthreads();

        uint32_t bCF = sb + (buf ? OCF1 : OCF0) + (wn * 16 + lrow) * 272 + lchk;
        uint32_t bDF = sb + (buf ? ODF1 : ODF0) + (wn * 16 + lrow) * 144 + lchk;

        float cf[2][4] = {}, df[2][4] = {};
        #pragma unroll
        for (int ks = 0; ks < 8; ks++) {       // cf: Xs[64x128] @ CF^T (warp 16x16)
            uint32_t a0, a1, a2, a3, b0, b1, b2, b3;
            LDSM4(a0, a1, a2, a3, aX0 + ks * 32);
            LDSM4(b0, b1, b2, b3, bCF + ks * 32);
            mma16(cf[0], a0, a1, a2, a3, b0, b2);
            mma16(cf[1], a0, a1, a2, a3, b1, b3);
        }
        #pragma unroll
        for (int ks = 0; ks < 4; ks++) {       // df: Ds[64x64] @ DF^T
            uint32_t a0, a1, a2, a3, b0, b1, b2, b3;
            LDSM4(a0, a1, a2, a3, aD0 + ks * 32);
            LDSM4(b0, b1, b2, b3, bDF + ks * 32);
            mma16(df[0], a0, a1, a2, a3, b0, b2);
            mma16(df[1], a0, a1, a2, a3, b1, b3);
        }
        // P = (cf+bc)*(df+128*bd) -> Pb (fp16)
        int hc = c * 64;
        #pragma unroll
        for (int nt = 0; nt < 2; nt++) {
            int col = wn * 16 + nt * 8 + 2 * t;
            int row = wm * 16 + g;
            float b0c = bc[hc + col], b1c = bc[hc + col + 1];
            float b0d = bd[hc + col], b1d = bd[hc + col + 1];
            float* f4 = cf[nt];
            float* d4 = df[nt];
            Ph[(row * 72 + col) >> 1] =
                __floats2half2_rn((f4[0] + b0c) * (d4[0] + b0d), (f4[1] + b1c) * (d4[1] + b1d));
            Ph[((row + 8) * 72 + col) >> 1] =
                __floats2half2_rn((f4[2] + b0c) * (d4[2] + b0d), (f4[3] + b1c) * (d4[3] + b1d));
        }

        if (i < 11) cp_wait<1>(); else cp_wait<0>();   // FC(i) complete
        __syncthreads();                                // Pb + FCb visible

        #pragma unroll
        for (int ks = 0; ks < 4; ks++) {       // fc: Pb[64x64] @ FC^T (warp 16x32, accumulate)
            uint32_t p0, p1, p2, p3, b0, b1, b2, b3, c0, c1, c2, c3;
            LDSM4(p0, p1, p2, p3, aP0 + ks * 32);
            LDSM4(b0, b1, b2, b3, bF0 + ks * 32);
            LDSM4(c0, c1, c2, c3, bF1 + ks * 32);
            mma16(hacc[0], p0, p1, p2, p3, b0, b2);
            mma16(hacc[1], p0, p1, p2, p3, b1, b3);
            mma16(hacc[2], p0, p1, p2, p3, c0, c2);
            mma16(hacc[3], p0, p1, p2, p3, c1, c3);
        }

        if (c == 3) {
            if (l < 2) {
                #pragma unroll
                for (int nt = 0; nt < 4; nt++) {
                    int col = wn * 32 + nt * 8 + 2 * t;
                    int row = wm * 16 + g;
                    float* h4 = hacc[nt];
                    Xh[(row * 136 + col) >> 1] =
                        __floats2half2_rn(h4[0] + tanh_fast(h4[0]), h4[1] + tanh_fast(h4[1]));
                    Xh[((row + 8) * 136 + col) >> 1] =
                        __floats2half2_rn(h4[2] + tanh_fast(h4[2]), h4[3] + tanh_fast(h4[3]));
                }
                if (tid < 256) {
                    bc[tid] = Wcf_b[(l + 1) * H_ + tid];
                    bd[tid] = 128.f * Wdf_b[(l + 1) * H_ + tid];
                }
                #pragma unroll
                for (int nt = 0; nt < 4; nt++)
                #pragma unroll
                for (int e = 0; e < 4; e++) hacc[nt][e] = 0.f;
            } else {
                #pragma unroll
                for (int nt = 0; nt < 4; nt++) {
                    int col = wn * 32 + nt * 8 + 2 * t;
                    float* h4 = hacc[nt];
                    pool += (h4[0] + tanh_fast(h4[0])) * vv[col];
                    pool += (h4[1] + tanh_fast(h4[1])) * vv[col + 1];
                    pool += (h4[2] + tanh_fast(h4[2])) * vv[col];
                    pool += (h4[3] + tanh_fast(h4[3])) * vv[col + 1];
                }
                rd[tid] = pool;
                __syncthreads();
                for (int s = 256; s > 0; s >>= 1) {
                    if (tid < s) rd[tid] += rd[tid + s];
                    __syncthreads();
                }
                if (tid == 0) atomicAdd(out + (bid >> 1), rd[0]);
            }
        }
        if (i < 11) { __syncthreads(); }   // protect buffers reused next iter
    }
}

// ---------------- launch ----------------
extern "C" void kernel_launch(void* const* d_in, const int* in_sizes, int n_in,
                              void* d_out, int out_size) {
    const float* x     = (const float*)d_in[0];
    const float* dist  = (const float*)d_in[1];
    const float* Wcf_w = (const float*)d_in[2];
    const float* Wcf_b = (const float*)d_in[3];
    const float* Wdf_w = (const float*)d_in[4];
    const float* Wdf_b = (const float*)d_in[5];
    const float* Wfc_w = (const float*)d_in[6];
    const float* fc0_w = (const float*)d_in[7];
    const float* fc0_b = (const float*)d_in[8];
    const float* out_w = (const float*)d_in[9];
    const float* out_b = (const float*)d_in[10];
    float* out = (float*)d_out;

    cudaFuncSetAttribute(dtnn_mma_kernel,
                         cudaFuncAttributeMaxDynamicSharedMemorySize, SMEMB);

    prep_reduce_kernel<<<141 + ROWS, 256>>>(dist, x, Wcf_w, Wdf_w, Wfc_w,
                                            fc0_w, fc0_b, out_w, out_b, out);
    dtnn_mma_kernel<<<128, 512, SMEMB>>>(Wcf_b, Wdf_b, out);
}

// round 15
// speedup vs baseline: 1.1406x; 1.1089x over previous
#include <cuda_runtime.h>
#include <cuda_fp16.h>
#include <cstdint>

#define B_   64
#define N_   128
#define F_   128
#define R_   64
#define H_   256
#define L_   3
#define ROWS (B_*N_)

// half images: row strides 136 halves (K=128), 72 halves (K=64)
#define XSB 17408   // 64*136*2
#define CFB 17408
#define DSB 9216    // 64*72*2
#define DFB 9216
#define FCB 18432   // 128*72*2

__device__ uint4 g_cf[12 * CFB / 16];
__device__ uint4 g_df[12 * DFB / 16];
__device__ uint4 g_fc[12 * FCB / 16];
__device__ uint4 g_xs[128 * XSB / 16];
__device__ uint4 g_ds[128 * DSB / 16];
__device__ float g_v[F_];

__device__ __forceinline__ float tanh_fast(float x) {
    float r; asm("tanh.approx.f32 %0, %1;" : "=f"(r) : "f"(x)); return r;
}
__device__ __forceinline__ uint32_t f2h2(float lo, float hi) {
    __half2 h = __floats2half2_rn(lo, hi);
    return *(uint32_t*)&h;
}
__device__ __forceinline__ void mma16(float* d, uint32_t a0, uint32_t a1, uint32_t a2, uint32_t a3,
                                      uint32_t b0, uint32_t b1) {
    asm volatile(
        "mma.sync.aligned.m16n8k16.row.col.f32.f16.f16.f32 "
        "{%0,%1,%2,%3},{%4,%5,%6,%7},{%8,%9},{%0,%1,%2,%3};"
        : "+f"(d[0]), "+f"(d[1]), "+f"(d[2]), "+f"(d[3])
        : "r"(a0), "r"(a1), "r"(a2), "r"(a3), "r"(b0), "r"(b1));
}
#define LDSM4(r0,r1,r2,r3,addr) \
    asm volatile("ldmatrix.sync.aligned.m8n8.x4.shared.b16 {%0,%1,%2,%3}, [%4];" \
        : "=r"(r0), "=r"(r1), "=r"(r2), "=r"(r3) : "r"(addr))
__device__ __forceinline__ void cpa16(uint32_t dst, const uint4* src) {
    asm volatile("cp.async.ca.shared.global [%0], [%1], 16;" :: "r"(dst), "l"(src));
}
#define CP_COMMIT() asm volatile("cp.async.commit_group;" ::: "memory")
template<int N>
__device__ __forceinline__ void cp_wait() {
    asm volatile("cp.async.wait_group %0;" :: "n"(N) : "memory");
}
template<int NC>
__device__ __forceinline__ void copy_img(uint32_t dst, const uint4* __restrict__ src, int tid) {
    #pragma unroll
    for (int i = tid; i < NC; i += 256) cpa16(dst + i * 16, src + i);
}
__device__ __forceinline__ uint32_t smem_u32(const void* p) {
    uint32_t a;
    asm("{ .reg .u64 t; cvta.to.shared.u64 t, %1; cvt.u32.u64 %0, t; }" : "=r"(a) : "l"(p));
    return a;
}
__device__ __forceinline__ void pack8(char* dst, const float* __restrict__ src) {
    float4 a = *(const float4*)src;
    float4 b = *(const float4*)(src + 4);
    uint4 o;
    o.x = f2h2(a.x, a.y); o.y = f2h2(a.z, a.w);
    o.z = f2h2(b.x, b.y); o.w = f2h2(b.z, b.w);
    *(uint4*)dst = o;
}

// ---------------- Kernel A: prep (141 blocks) + streaming reduce (8192 blocks) ----------------
__global__ void prep_reduce_kernel(const float* __restrict__ dist, const float* __restrict__ x,
                                   const float* __restrict__ Wcf_w, const float* __restrict__ Wdf_w,
                                   const float* __restrict__ Wfc_w,
                                   const float* __restrict__ fc0_w, const float* __restrict__ fc0_b,
                                   const float* __restrict__ out_w, const float* __restrict__ out_b,
                                   float* __restrict__ out) {
    int bid = blockIdx.x, tid = threadIdx.x;
    if (bid >= 141) {                      // ---- reduce one row (32KB) ----
        int row = bid - 141;
        const float4* p = (const float4*)(dist + (size_t)row * (N_ * R_));
        float4 acc = make_float4(0.f, 0.f, 0.f, 0.f);
        #pragma unroll
        for (int t = 0; t < 8; t++) {
            float4 v = __ldcs(&p[tid + t * 256]);
            acc.x += v.x; acc.y += v.y; acc.z += v.z; acc.w += v.w;
        }
        __shared__ float4 s[256];
        s[tid] = acc;
        __syncthreads();
        if (tid < 16) {
            float4 a = s[tid];
            #pragma unroll
            for (int m = 1; m < 16; m++) {
                float4 b = s[tid + 16 * m];
                a.x += b.x; a.y += b.y; a.z += b.z; a.w += b.w;
            }
            char* dp = (char*)g_ds + (row >> 6) * DSB + (row & 63) * 144 + tid * 8;
            uint2 o; o.x = f2h2(a.x, a.y); o.y = f2h2(a.z, a.w);
            *(uint2*)dp = o;
        }
    } else if (bid < 128) {                // ---- x tile image ----
        char* dst = (char*)g_xs + (size_t)bid * XSB;
        const float* src = x + (size_t)bid * 64 * 128;
        #pragma unroll
        for (int i = 0; i < 4; i++) {
            int oct = tid + i * 256;
            int row = oct >> 4, ko = oct & 15;
            pack8(dst + row * 272 + ko * 16, src + row * 128 + ko * 8);
        }
    } else if (bid < 140) {                // ---- weight chunk images ----
        int wi = bid - 128, l = wi >> 2, c = wi & 3;
        char* dcf = (char*)g_cf + (size_t)wi * CFB;
        const float* scf = Wcf_w + (size_t)l * 32768 + c * 8192;
        #pragma unroll
        for (int i = 0; i < 4; i++) {
            int oct = tid + i * 256;
            int row = oct >> 4, ko = oct & 15;
            pack8(dcf + row * 272 + ko * 16, scf + row * 128 + ko * 8);
        }
        char* ddf = (char*)g_df + (size_t)wi * DFB;
        const float* sdf = Wdf_w + (size_t)l * 16384 + c * 4096;
        #pragma unroll
        for (int i = 0; i < 2; i++) {
            int oct = tid + i * 256;
            int row = oct >> 3, ko = oct & 7;
            pack8(ddf + row * 144 + ko * 16, sdf + row * 64 + ko * 8);
        }
        char* dfc = (char*)g_fc + (size_t)wi * FCB;
        const float* sfc = Wfc_w + (size_t)l * 32768 + c * 64;
        #pragma unroll
        for (int i = 0; i < 4; i++) {
            int oct = tid + i * 256;
            int row = oct >> 3, ko = oct & 7;
            pack8(dfc + row * 144 + ko * 16, sfc + row * 256 + ko * 8);
        }
    } else {                               // ---- fold head + init out ----
        if (tid < 128) {
            float a = 0.f;
            #pragma unroll 8
            for (int c = 0; c < 256; c++) a += out_w[c] * fc0_w[c * F_ + tid];
            g_v[tid] = a;
        }
        __shared__ float cs;
        if (tid == 0) {
            float s = out_b[0];
            for (int c = 0; c < 256; c++) s += out_w[c] * fc0_b[c];
            cs = s;
        }
        __syncthreads();
        if (tid < B_) out[tid] = cs;
    }
}

// ---------------- Kernel B: fp16 mma, 128 CTAs x 64 rows, 256 threads ----------------
// 2 syncs + 1 wait per iter; FC double-buffered; Ds fragments register-cached.
enum {
    OXS  = 0,
    ODS  = OXS + XSB,     // 17408
    OPB  = ODS + DSB,     // 26624
    OCF0 = OPB + DSB,     // 35840
    OCF1 = OCF0 + CFB,    // 53248
    ODF0 = OCF1 + CFB,    // 70656
    ODF1 = ODF0 + DFB,    // 79872
    OFC0 = ODF1 + DFB,    // 89088
    OFC1 = OFC0 + FCB,    // 107520
    OBC  = OFC1 + FCB,    // 125952
    OBD  = OBC + 1024,
    OVV  = OBD + 1024,
    ORD  = OVV + 512,
    SMEMB = ORD + 1024    // 129536 B
};

__global__ __launch_bounds__(256, 1)
void dtnn_mma_kernel(const float* __restrict__ Wcf_b, const float* __restrict__ Wdf_b,
                     float* __restrict__ out) {
    extern __shared__ char smc[];
    float* bc = (float*)(smc + OBC);
    float* bd = (float*)(smc + OBD);
    float* vv = (float*)(smc + OVV);
    float* rd = (float*)(smc + ORD);
    __half2* Ph = (__half2*)(smc + OPB);
    __half2* Xh = (__half2*)(smc + OXS);
    uint32_t sb = smem_u32(smc);

    int tid = threadIdx.x, lane = tid & 31, w = tid >> 5;
    int g = lane >> 2, t = lane & 3;
    int wm = w & 1, wn = w >> 1;          // warp grid: 2 (M=32 rows) x 4 (N)
    int bid = blockIdx.x;

    int lrow = (lane & 7) + ((lane >> 3) & 1) * 8;
    int lchk = ((lane >> 4) & 1) * 16;
    uint32_t aX0 = sb + OXS + (wm * 32 + lrow) * 272 + lchk;
    uint32_t aX1 = aX0 + 16 * 272;
    uint32_t aD0 = sb + ODS + (wm * 32 + lrow) * 144 + lchk;
    uint32_t aD1 = aD0 + 16 * 144;
    uint32_t aP0 = sb + OPB + (wm * 32 + lrow) * 144 + lchk;
    uint32_t aP1 = aP0 + 16 * 144;
    uint32_t bFA = sb + OFC0 + (wn * 32 + lrow) * 144 + lchk;
    uint32_t bFB = sb + OFC1 + (wn * 32 + lrow) * 144 + lchk;

    // prologue: Xs, Ds, CF0, DF0, FC0
    copy_img<XSB/16>(sb + OXS, g_xs + bid * (XSB/16), tid);
    copy_img<DSB/16>(sb + ODS, g_ds + bid * (DSB/16), tid);
    copy_img<CFB/16>(sb + OCF0, g_cf, tid);
    copy_img<DFB/16>(sb + ODF0, g_df, tid);
    CP_COMMIT();
    copy_img<FCB/16>(sb + OFC0, g_fc, tid);
    CP_COMMIT();
    bc[tid] = Wcf_b[tid];
    bd[tid] = 128.f * Wdf_b[tid];
    if (tid < 128) vv[tid] = g_v[tid];
    cp_wait<0>();
    __syncthreads();

    // register-cache the Ds fragments (static for the whole kernel)
    uint32_t adc[4][8];
    #pragma unroll
    for (int ks = 0; ks < 4; ks++) {
        LDSM4(adc[ks][0], adc[ks][1], adc[ks][2], adc[ks][3], aD0 + ks * 32);
        LDSM4(adc[ks][4], adc[ks][5], adc[ks][6], adc[ks][7], aD1 + ks * 32);
    }

    float hacc[2][4][4] = {};
    float pool = 0.f;

    for (int i = 0; i < 12; i++) {
        int l = i >> 2, c = i & 3, buf = i & 1;

        cp_wait<0>();        // CFDF(i) + FC(i) complete (issued one full iter ago)
        __syncthreads();     // SYNC-A: copies visible; prior iter fully done

        if (i < 11) {        // prefetch CFDF(i+1), FC(i+1) into the INACTIVE buffers
            copy_img<CFB/16>(sb + (buf ? OCF0 : OCF1), g_cf + (i + 1) * (CFB/16), tid);
            copy_img<DFB/16>(sb + (buf ? ODF0 : ODF1), g_df + (i + 1) * (DFB/16), tid);
            CP_COMMIT();
            copy_img<FCB/16>(sb + (buf ? OFC0 : OFC1), g_fc + (i + 1) * (FCB/16), tid);
            CP_COMMIT();
        }

        uint32_t bCF = sb + (buf ? OCF1 : OCF0) + (wn * 16 + lrow) * 272 + lchk;
        uint32_t bDF = sb + (buf ? ODF1 : ODF0) + (wn * 16 + lrow) * 144 + lchk;

        float cf[2][2][4] = {}, df[2][2][4] = {};
        #pragma unroll
        for (int ks = 0; ks < 8; ks++) {       // cf: Xs[64x128] @ CF^T
            uint32_t a0, a1, a2, a3, a4, a5, a6, a7, b0, b1, b2, b3;
            LDSM4(a0, a1, a2, a3, aX0 + ks * 32);
            LDSM4(a4, a5, a6, a7, aX1 + ks * 32);
            LDSM4(b0, b1, b2, b3, bCF + ks * 32);
            mma16(cf[0][0], a0, a1, a2, a3, b0, b2);
            mma16(cf[0][1], a0, a1, a2, a3, b1, b3);
            mma16(cf[1][0], a4, a5, a6, a7, b0, b2);
            mma16(cf[1][1], a4, a5, a6, a7, b1, b3);
        }
        #pragma unroll
        for (int ks = 0; ks < 4; ks++) {       // df: cached Ds frags @ DF^T
            uint32_t b0, b1, b2, b3;
            LDSM4(b0, b1, b2, b3, bDF + ks * 32);
            mma16(df[0][0], adc[ks][0], adc[ks][1], adc[ks][2], adc[ks][3], b0, b2);
            mma16(df[0][1], adc[ks][0], adc[ks][1], adc[ks][2], adc[ks][3], b1, b3);
            mma16(df[1][0], adc[ks][4], adc[ks][5], adc[ks][6], adc[ks][7], b0, b2);
            mma16(df[1][1], adc[ks][4], adc[ks][5], adc[ks][6], adc[ks][7], b1, b3);
        }
        // P = (cf+bc)*(df+128*bd) -> Pb (fp16)
        int hc = c * 64;
        #pragma unroll
        for (int mt = 0; mt < 2; mt++)
        #pragma unroll
        for (int nt = 0; nt < 2; nt++) {
            int col = wn * 16 + nt * 8 + 2 * t;
            int row = wm * 32 + mt * 16 + g;
            float b0c = bc[hc + col], b1c = bc[hc + col + 1];
            float b0d = bd[hc + col], b1d = bd[hc + col + 1];
            float* f4 = cf[mt][nt];
            float* d4 = df[mt][nt];
            Ph[(row * 72 + col) >> 1] =
                __floats2half2_rn((f4[0] + b0c) * (d4[0] + b0d), (f4[1] + b1c) * (d4[1] + b1d));
            Ph[((row + 8) * 72 + col) >> 1] =
                __floats2half2_rn((f4[2] + b0c) * (d4[2] + b0d), (f4[3] + b1c) * (d4[3] + b1d));
        }

        __syncthreads();     // SYNC-B: Pb ready (FC(i) resident since SYNC-A)

        uint32_t f0 = (buf ? bFB : bFA);
        uint32_t f1 = f0 + 16 * 144;
        #pragma unroll
        for (int ks = 0; ks < 4; ks++) {       // fc: Pb[64x64] @ FC^T (accumulate)
            uint32_t p0, p1, p2, p3, p4, p5, p6, p7, b0, b1, b2, b3, c0, c1, c2, c3;
            LDSM4(p0, p1, p2, p3, aP0 + ks * 32);
            LDSM4(p4, p5, p6, p7, aP1 + ks * 32);
            LDSM4(b0, b1, b2, b3, f0 + ks * 32);
            LDSM4(c0, c1, c2, c3, f1 + ks * 32);
            mma16(hacc[0][0], p0, p1, p2, p3, b0, b2);
            mma16(hacc[0][1], p0, p1, p2, p3, b1, b3);
            mma16(hacc[0][2], p0, p1, p2, p3, c0, c2);
            mma16(hacc[0][3], p0, p1, p2, p3, c1, c3);
            mma16(hacc[1][0], p4, p5, p6, p7, b0, b2);
            mma16(hacc[1][1], p4, p5, p6, p7, b1, b3);
            mma16(hacc[1][2], p4, p5, p6, p7, c0, c2);
            mma16(hacc[1][3], p4, p5, p6, p7, c1, c3);
        }

        if (c == 3) {
            if (l < 2) {
                #pragma unroll
                for (int mt = 0; mt < 2; mt++)
                #pragma unroll
                for (int nt = 0; nt < 4; nt++) {
                    int col = wn * 32 + nt * 8 + 2 * t;
                    int row = wm * 32 + mt * 16 + g;
                    float* h4 = hacc[mt][nt];
                    Xh[(row * 136 + col) >> 1] =
                        __floats2half2_rn(h4[0] + tanh_fast(h4[0]), h4[1] + tanh_fast(h4[1]));
                    Xh[((row + 8) * 136 + col) >> 1] =
                        __floats2half2_rn(h4[2] + tanh_fast(h4[2]), h4[3] + tanh_fast(h4[3]));
                }
                bc[tid] = Wcf_b[(l + 1) * H_ + tid];
                bd[tid] = 128.f * Wdf_b[(l + 1) * H_ + tid];
                #pragma unroll
                for (int mt = 0; mt < 2; mt++)
                #pragma unroll
                for (int nt = 0; nt < 4; nt++)
                #pragma unroll
                for (int e = 0; e < 4; e++) hacc[mt][nt][e] = 0.f;
            } else {
                #pragma unroll
                for (int mt = 0; mt < 2; mt++)
                #pragma unroll
                for (int nt = 0; nt < 4; nt++) {
                    int col = wn * 32 + nt * 8 + 2 * t;
                    float* h4 = hacc[mt][nt];
                    pool += (h4[0] + tanh_fast(h4[0])) * vv[col];
                    pool += (h4[1] + tanh_fast(h4[1])) * vv[col + 1];
                    pool += (h4[2] + tanh_fast(h4[2])) * vv[col];
                    pool += (h4[3] + tanh_fast(h4[3])) * vv[col + 1];
                }
                rd[tid] = pool;
                __syncthreads();
                for (int s = 128; s > 0; s >>= 1) {
                    if (tid < s) rd[tid] += rd[tid + s];
                    __syncthreads();
                }
                if (tid == 0) atomicAdd(out + (bid >> 1), rd[0]);
            }
        }
    }
}

// ---------------- launch ----------------
extern "C" void kernel_launch(void* const* d_in, const int* in_sizes, int n_in,
                              void* d_out, int out_size) {
    const float* x     = (const float*)d_in[0];
    const float* dist  = (const float*)d_in[1];
    const float* Wcf_w = (const float*)d_in[2];
    const float* Wcf_b = (const float*)d_in[3];
    const float* Wdf_w = (const float*)d_in[4];
    const float* Wdf_b = (const float*)d_in[5];
    const float* Wfc_w = (const float*)d_in[6];
    const float* fc0_w = (const float*)d_in[7];
    const float* fc0_b = (const float*)d_in[8];
    const float* out_w = (const float*)d_in[9];
    const float* out_b = (const float*)d_in[10];
    float* out = (float*)d_out;

    cudaFuncSetAttribute(dtnn_mma_kernel,
                         cudaFuncAttributeMaxDynamicSharedMemorySize, SMEMB);

    prep_reduce_kernel<<<141 + ROWS, 256>>>(dist, x, Wcf_w, Wdf_w, Wfc_w,
                                            fc0_w, fc0_b, out_w, out_b, out);
    dtnn_mma_kernel<<<128, 256, SMEMB>>>(Wcf_b, Wdf_b, out);
}